// round 6
// baseline (speedup 1.0000x reference)
#include <cuda_runtime.h>
#include <math.h>

#define Bx 32
#define Nx 500
#define T0x 13
#define Ex 2000
#define EHx 300
#define Cx 40

// ---------------- scratch ----------------
__device__ float g_Xa[(long)Bx*Cx*13*Nx];
__device__ float g_Xb[(long)Bx*Cx*11*Nx];
__device__ float g_H [(long)Bx*7*Cx*11*Nx];
__device__ float g_G [(long)Bx*Cx*11*Nx];
__device__ float g_S1[(long)Bx*320*11*Nx];
__device__ float g_S2[(long)Bx*320*9*Nx];
__device__ float g_E1[(long)Bx*640*7*Nx];
__device__ float g_nin[Bx*T0x*Nx];
__device__ double g_part[256];
__device__ float g_mstd[2];
__device__ float g_adp[Nx*Nx];
__device__ float g_xm[Bx*Cx*Nx];
__device__ float g_scf[Bx*Ex], g_scb[Bx*Ex];
__device__ float g_uf[Bx*EHx], g_ub[Bx*EHx];
__device__ float g_ef[Bx*Ex], g_eb[Bx*Ex];
__device__ float g_bn[2*Cx];
__device__ int   g_islast[Ex];
__device__ float g_diagf[Nx], g_diagb[Nx];
__device__ int   g_cntd[Nx], g_cnts[Nx], g_offd[Nx+1], g_offs[Nx+1];
__device__ int   g_dnode[Ex], g_deid[Ex]; __device__ float g_dw[Ex];
__device__ int   g_snode[Ex], g_seid[Ex]; __device__ float g_sw[Ex];
__device__ float g_WT[3*Cx*7*Cx];

static inline long divup(long a, long b){ return (a+b-1)/b; }

// ---------------- input stats ----------------
__global__ void k_instats1(const float* __restrict__ in, int n){
  __shared__ double ss[256], sq[256];
  int tid = threadIdx.x; double s=0, q=0;
  for (int i = blockIdx.x*256+tid; i < n; i += gridDim.x*256){ float v=in[i]; s+=v; q+=(double)v*v; }
  ss[tid]=s; sq[tid]=q; __syncthreads();
  for (int o=128;o>0;o>>=1){ if(tid<o){ ss[tid]+=ss[tid+o]; sq[tid]+=sq[tid+o]; } __syncthreads(); }
  if (!tid){ g_part[blockIdx.x]=ss[0]; g_part[128+blockIdx.x]=sq[0]; }
}
__global__ void k_instats2(int nblk, int n){
  __shared__ double ss[128], sq[128];
  int tid = threadIdx.x;
  ss[tid] = (tid<nblk)? g_part[tid]:0.0; sq[tid] = (tid<nblk)? g_part[128+tid]:0.0;
  __syncthreads();
  for (int o=64;o>0;o>>=1){ if(tid<o){ ss[tid]+=ss[tid+o]; sq[tid]+=sq[tid+o]; } __syncthreads(); }
  if (!tid){ double m=ss[0]/n, v=sq[0]/n-m*m; g_mstd[0]=(float)m; g_mstd[1]=(float)rsqrt(v+1e-5); }
}
__global__ void k_norm(const float* __restrict__ in){
  int i = blockIdx.x*256+threadIdx.x; if (i >= Bx*T0x*Nx) return;
  int t = i%T0x; int r = i/T0x; int n = r%Nx; int b = r/Nx;
  g_nin[(b*T0x+t)*Nx+n] = (in[(b*Nx+n)*T0x+t]-g_mstd[0])*g_mstd[1];
}
__global__ void k_start(const float* __restrict__ sw, const float* __restrict__ sb){
  long i = blockIdx.x*256L+threadIdx.x; long tot=(long)Bx*Cx*T0x*Nx; if (i>=tot) return;
  int n = i%Nx; long r=i/Nx; int t = r%T0x; r/=T0x; int c = r%Cx; int b = r/Cx;
  g_Xa[i] = sw[c]*g_nin[(b*T0x+t)*Nx+n] + sb[c];
}
// ---------------- adp ----------------
__global__ void k_adpmm(const float* __restrict__ v1, const float* __restrict__ v2){
  int i = blockIdx.x*256+threadIdx.x; if (i>=Nx*Nx) return;
  int n=i/Nx, m=i%Nx; float s=0.f;
  #pragma unroll
  for (int k=0;k<10;k++) s += v1[n*10+k]*v2[k*Nx+m];
  g_adp[i] = fmaxf(s,0.f);
}
__global__ void k_softmax(){
  int n = blockIdx.x, tid = threadIdx.x;
  __shared__ float red[256];
  float mx=-1e30f;
  for (int m=tid;m<Nx;m+=256) mx=fmaxf(mx,g_adp[n*Nx+m]);
  red[tid]=mx; __syncthreads();
  for (int o=128;o>0;o>>=1){ if(tid<o) red[tid]=fmaxf(red[tid],red[tid+o]); __syncthreads(); }
  mx=red[0]; __syncthreads();
  float s=0.f;
  for (int m=tid;m<Nx;m+=256) s+=expf(g_adp[n*Nx+m]-mx);
  red[tid]=s; __syncthreads();
  for (int o=128;o>0;o>>=1){ if(tid<o) red[tid]+=red[tid+o]; __syncthreads(); }
  float inv=1.f/red[0];
  for (int m=tid;m<Nx;m+=256) g_adp[n*Nx+m]=expf(g_adp[n*Nx+m]-mx)*inv;
}
// ---------------- edge structures ----------------
__global__ void k_islast(const int* __restrict__ idx){
  int e = blockIdx.x*128+threadIdx.x; if (e>=Ex) return;
  int a=idx[e], b=idx[Ex+e]; int last=1;
  for (int f=e+1;f<Ex;f++) if (idx[f]==a && idx[Ex+f]==b){ last=0; break; }
  g_islast[e]=last;
}
__global__ void k_keep(const int* __restrict__ idx, const float* __restrict__ Af, const float* __restrict__ Ab){
  int m = blockIdx.x*128+threadIdx.x; if (m>=Nx) return;
  float keep=1.f;
  for (int e=0;e<Ex;e++) if (idx[e]==m && idx[Ex+e]==m){ keep=0.f; break; }
  g_diagf[m]=keep*Af[m*Nx+m]; g_diagb[m]=keep*Ab[m*Nx+m];
  g_cntd[m]=0; g_cnts[m]=0;
}
__global__ void k_count(const int* __restrict__ idx){
  int e = blockIdx.x*128+threadIdx.x; if (e>=Ex) return;
  if (g_islast[e]){ atomicAdd(&g_cntd[idx[Ex+e]],1); atomicAdd(&g_cnts[idx[e]],1); }
}
__global__ void k_scan(){
  int s=0; for (int i=0;i<Nx;i++){ g_offd[i]=s; s+=g_cntd[i]; } g_offd[Nx]=s;
  s=0;     for (int i=0;i<Nx;i++){ g_offs[i]=s; s+=g_cnts[i]; } g_offs[Nx]=s;
}
__global__ void k_fill(const int* __restrict__ idx, const float* __restrict__ Af, const float* __restrict__ Ab){
  int m = blockIdx.x*64+threadIdx.x; if (m>=Nx) return;
  int pd=g_offd[m], ps=g_offs[m];
  for (int e=0;e<Ex;e++){
    if (!g_islast[e]) continue;
    int i0=idx[e], i1=idx[Ex+e];
    if (i1==m){ g_dnode[pd]=i0; g_deid[pd]=e; g_dw[pd]=Af[i0*Nx+m]; pd++; }
    if (i0==m){ g_snode[ps]=i1; g_seid[ps]=e; g_sw[ps]=Ab[i1*Nx+m]; ps++; }
  }
}
__global__ void k_transW(const float* __restrict__ W){
  int i = blockIdx.x*256+threadIdx.x; if (i>=3*Cx*7*Cx) return;
  int c = i%(7*Cx); int r = i/(7*Cx); int o = r%Cx; int blk = r/Cx;
  g_WT[i] = W[(blk*7*Cx + c)*Cx + o];
}
// ---------------- per-block small ----------------
__global__ void k_xmean(const float* __restrict__ X, int Told){
  int i = blockIdx.x*256+threadIdx.x; if (i>=Bx*Cx*Nx) return;
  int n=i%Nx; int r=i/Nx; int c=r%Cx; int b=r/Cx;
  const float* p = X + ((long)(b*Cx+c))*Told*Nx + n;
  float s=0.f; for (int t=0;t<Told;t++) s += p[(long)t*Nx];
  g_xm[i] = s/Told;
}
__global__ void k_escore(const int* __restrict__ idx, const float* __restrict__ vsf,
    const float* __restrict__ vdf, const float* __restrict__ vsb, const float* __restrict__ vdb){
  int i = blockIdx.x*128+threadIdx.x; if (i>=Bx*Ex) return;
  int e=i%Ex, b=i/Ex; int i0=idx[e], i1=idx[Ex+e];
  float sf=0.f, sb=0.f;
  for (int c=0;c<Cx;c++){
    float s=g_xm[(b*Cx+c)*Nx+i0], d=g_xm[(b*Cx+c)*Nx+i1];
    sf += s*vsf[c]+d*vdf[c]; sb += s*vsb[c]+d*vdb[c];
  }
  g_scf[i]=sf; g_scb[i]=sb;
}
__global__ void k_edge1(const float* __restrict__ G0){
  int i = blockIdx.x*128+threadIdx.x; if (i>=Bx*EHx) return;
  int h=i%EHx, b=i/EHx;
  float uf=0.f, ub=0.f;
  for (int e=0;e<Ex;e++){ float g=G0[e*EHx+h]; uf+=g_scf[b*Ex+e]*g; ub+=g_scb[b*Ex+e]*g; }
  g_uf[i]=uf; g_ub[i]=ub;
}
__global__ void k_edge2(const float* __restrict__ G1, const float* __restrict__ wf, const float* __restrict__ wb){
  int i = blockIdx.x*128+threadIdx.x; if (i>=Bx*Ex) return;
  int e=i%Ex, b=i/Ex;
  float f=0.f, bb=0.f;
  for (int h=0;h<EHx;h++){ float g=G1[h*Ex+e]; f+=g_uf[b*EHx+h]*wf[h]*g; bb+=g_ub[b*EHx+h]*wb[h]*g; }
  g_ef[i]=1.f/(1.f+expf(-f)); g_eb[i]=1.f/(1.f+expf(-bb));
}
__global__ void k_dconv(const float* __restrict__ X, int Told,
    const float* __restrict__ Wf, const float* __restrict__ bf,
    const float* __restrict__ Wg, const float* __restrict__ bg, int Tb){
  long i = blockIdx.x*256L+threadIdx.x; long tot=(long)Bx*Cx*Tb*Nx; if (i>=tot) return;
  int n=i%Nx; long r=i/Nx; int t=r%Tb; r/=Tb; int o=r%Cx; int b=r/Cx;
  const float* xb = X + (long)b*Cx*Told*Nx;
  float f=bf[o], g=bg[o];
  for (int c=0;c<Cx;c++){
    float x0 = xb[((long)c*Told+t)*Nx+n];
    float x2 = xb[((long)c*Told+t+2)*Nx+n];
    f += Wf[(o*Cx+c)*2]*x0 + Wf[(o*Cx+c)*2+1]*x2;
    g += Wg[(o*Cx+c)*2]*x0 + Wg[(o*Cx+c)*2+1]*x2;
  }
  g_H[(((long)b*7*Cx+o)*Tb+t)*Nx+n] = tanhf(f)/(1.f+expf(-g));
}
__global__ void k_shop(int Tb, int inOff, int outOff, int fwd){
  long i = blockIdx.x*256L+threadIdx.x; long tot=(long)Bx*Cx*Tb*Nx; if (i>=tot) return;
  int m=i%Nx; long r=i/Nx; int t=r%Tb; r/=Tb; int c=r%Cx; int b=r/Cx;
  const int* off  = fwd? g_offd : g_offs;
  const int* node = fwd? g_dnode: g_snode;
  const int* eid  = fwd? g_deid : g_seid;
  const float* w  = fwd? g_dw   : g_sw;
  const float* dg = fwd? g_diagf: g_diagb;
  const float* gate = (fwd? g_ef : g_eb) + (long)b*Ex;
  long base = ((long)b*7*Cx + c)*Tb*Nx + (long)t*Nx;
  const float* inp = g_H + (long)inOff*Tb*Nx;
  float v = dg[m]*inp[base+m];
  for (int j=off[m]; j<off[m+1]; j++)
    v += gate[eid[j]]*w[j]*inp[base+node[j]];
  g_H[(long)outOff*Tb*Nx + base + m] = v;
}
// ---------------- generic GEMM ----------------
__global__ void k_gemm(const float* __restrict__ A, const float* __restrict__ B, float* __restrict__ C,
    int M, int N, int K, long sA, long sB, long sC,
    const float* __restrict__ bias, const float* __restrict__ acc,
    long sAcc, int ldAcc, int accOff, int act){
  int b = blockIdx.z;
  A += (long)b*sA; B += (long)b*sB; C += (long)b*sC;
  int row0 = blockIdx.y*64, col0 = blockIdx.x*64;
  __shared__ float As[16][65], Bs[16][65];
  int tid = threadIdx.x, tx = tid&15, ty = tid>>4;
  float av[4][4] = {};
  for (int k0=0; k0<K; k0+=16){
    int ak = tid&15, am = tid>>4;
    #pragma unroll
    for (int i=0;i<4;i++){
      int m=row0+am+i*16, k=k0+ak;
      As[ak][am+i*16] = (m<M && k<K)? A[(long)m*K+k] : 0.f;
    }
    int bn = tid&63, bk = tid>>6;
    #pragma unroll
    for (int i=0;i<4;i++){
      int k=k0+bk+i*4, n=col0+bn;
      Bs[bk+i*4][bn] = (k<K && n<N)? B[(long)k*N+n] : 0.f;
    }
    __syncthreads();
    #pragma unroll
    for (int kk=0;kk<16;kk++){
      float af[4], bf[4];
      #pragma unroll
      for (int i=0;i<4;i++) af[i]=As[kk][ty+i*16];
      #pragma unroll
      for (int j=0;j<4;j++) bf[j]=Bs[kk][tx+j*16];
      #pragma unroll
      for (int i=0;i<4;i++)
        #pragma unroll
        for (int j=0;j<4;j++) av[i][j] += af[i]*bf[j];
    }
    __syncthreads();
  }
  #pragma unroll
  for (int i=0;i<4;i++){
    int m=row0+ty+i*16; if (m>=M) continue;
    float bv = bias? bias[m] : 0.f;
    #pragma unroll
    for (int j=0;j<4;j++){
      int n=col0+tx+j*16; if (n>=N) continue;
      float v = av[i][j] + bv;
      if (acc) v += acc[(long)b*sAcc + (long)m*ldAcc + n + accOff];
      if (act==1) v = v>0.f? v : 0.01f*v;
      C[(long)m*N+n] = v;
    }
  }
}
// ---------------- BN ----------------
__global__ void k_bnstats(const float* __restrict__ X, int Tb){
  int c = blockIdx.x, tid = threadIdx.x;
  __shared__ float ss[256], sq[256];
  long per = (long)Tb*Nx, tot = (long)Bx*per;
  float s=0.f, q=0.f;
  for (long i=tid;i<tot;i+=256){
    int b = i/per; long r = i%per;
    float v = X[((long)b*Cx+c)*per + r];
    s+=v; q+=v*v;
  }
  ss[tid]=s; sq[tid]=q; __syncthreads();
  for (int o=128;o>0;o>>=1){ if(tid<o){ ss[tid]+=ss[tid+o]; sq[tid]+=sq[tid+o]; } __syncthreads(); }
  if (!tid){ float m=ss[0]/tot, v=sq[0]/tot-m*m; g_bn[c]=m; g_bn[Cx+c]=rsqrtf(v+1e-5f); }
}
__global__ void k_bnapply1(const float* __restrict__ G, const float* __restrict__ Xres, int Told,
    float* __restrict__ Xn, int Tb, const float* __restrict__ ga, const float* __restrict__ be){
  long i = blockIdx.x*256L+threadIdx.x; long tot=(long)Bx*Cx*Tb*Nx; if (i>=tot) return;
  int n=i%Nx; long r=i/Nx; int t=r%Tb; r/=Tb; int c=r%Cx; int b=r/Cx;
  float v = ga[c]*(G[i]-g_bn[c])*g_bn[Cx+c] + be[c];
  Xn[i] = v + Xres[((long)(b*Cx+c)*Told + t+2)*Nx + n];
}
__global__ void k_bnapply2(float* __restrict__ X, int Tb, const float* __restrict__ ga, const float* __restrict__ be){
  long i = blockIdx.x*256L+threadIdx.x; long tot=(long)Bx*Cx*Tb*Nx; if (i>=tot) return;
  long per=(long)Tb*Nx; int c = (int)((i/per)%Cx);
  X[i] = ga[c]*(X[i]-g_bn[c])*g_bn[Cx+c] + be[c];
}
__global__ void k_leaky(float* __restrict__ X, long tot){
  long i = blockIdx.x*256L+threadIdx.x; if (i>=tot) return;
  float v=X[i]; X[i] = v>0.f? v : 0.01f*v;
}
__global__ void k_end2(const float* __restrict__ W, const float* __restrict__ bb, float* __restrict__ out){
  long i = blockIdx.x*128L+threadIdx.x; long tot=(long)Bx*12*7*Nx; if (i>=tot) return;
  int n=i%Nx; long r=i/Nx; int t=r%7; r/=7; int o=r%12; int b=r/12;
  float v = bb[o];
  const float* e = g_E1 + (long)b*640*7*Nx + (long)t*Nx + n;
  for (int k=0;k<640;k++) v += e[(long)k*7*Nx]*W[o*640+k];
  out[((long)(b*12+o)*Nx + n)*7 + t] = v;
}

extern "C" void kernel_launch(void* const* d_in, const int* in_sizes, int n_in,
                              void* d_out, int out_size){
  const float* in  =(const float*)d_in[0];
  const float* Af  =(const float*)d_in[1];
  const float* Ab  =(const float*)d_in[2];
  const int*   idx =(const int*)  d_in[3];
  const float* G0  =(const float*)d_in[4];
  const float* G1  =(const float*)d_in[5];
  const float* nv1 =(const float*)d_in[6];
  const float* nv2 =(const float*)d_in[7];
  const float* wef =(const float*)d_in[8];
  const float* web =(const float*)d_in[9];
  const float* vsf =(const float*)d_in[10];
  const float* vdf =(const float*)d_in[11];
  const float* vsb =(const float*)d_in[12];
  const float* vdb =(const float*)d_in[13];
  const float* sw  =(const float*)d_in[14];
  const float* sb  =(const float*)d_in[15];
  const float* fw  =(const float*)d_in[16];
  const float* fb  =(const float*)d_in[17];
  const float* gw  =(const float*)d_in[18];
  const float* gb  =(const float*)d_in[19];
  const float* gcw =(const float*)d_in[20];
  const float* gcb =(const float*)d_in[21];
  const float* bgg =(const float*)d_in[22];
  const float* bgb =(const float*)d_in[23];
  const float* bng =(const float*)d_in[24];
  const float* bnb =(const float*)d_in[25];
  const float* skw =(const float*)d_in[26];
  const float* skb =(const float*)d_in[27];
  const float* e1w =(const float*)d_in[28];
  const float* e1b =(const float*)d_in[29];
  const float* e2w =(const float*)d_in[30];
  const float* e2b =(const float*)d_in[31];
  float* out = (float*)d_out;

  float *Xa,*Xb,*H,*G,*S1,*S2,*E1,*ADP,*WT;
  cudaGetSymbolAddress((void**)&Xa, g_Xa);
  cudaGetSymbolAddress((void**)&Xb, g_Xb);
  cudaGetSymbolAddress((void**)&H,  g_H);
  cudaGetSymbolAddress((void**)&G,  g_G);
  cudaGetSymbolAddress((void**)&S1, g_S1);
  cudaGetSymbolAddress((void**)&S2, g_S2);
  cudaGetSymbolAddress((void**)&E1, g_E1);
  cudaGetSymbolAddress((void**)&ADP,g_adp);
  cudaGetSymbolAddress((void**)&WT, g_WT);

  int tin = Bx*T0x*Nx;
  k_instats1<<<128,256>>>(in, tin);
  k_instats2<<<1,128>>>(128, tin);
  k_norm<<<(int)divup(tin,256),256>>>(in);
  { long t=(long)Bx*Cx*T0x*Nx; k_start<<<(int)divup(t,256),256>>>(sw, sb); }
  k_adpmm<<<(int)divup(Nx*Nx,256),256>>>(nv1,nv2);
  k_softmax<<<Nx,256>>>();
  k_islast<<<(int)divup(Ex,128),128>>>(idx);
  k_keep<<<(int)divup(Nx,128),128>>>(idx, Af, Ab);
  k_count<<<(int)divup(Ex,128),128>>>(idx);
  k_scan<<<1,1>>>();
  k_fill<<<(int)divup(Nx,64),64>>>(idx, Af, Ab);
  k_transW<<<(int)divup(3*Cx*7*Cx,256),256>>>(gcw);

  float* Xcur = Xa; float* Xnext = Xb;
  float* Sprev = 0;  float* Scur = S1;
  int Told = 13, Tprev = 0;
  for (int blk=0; blk<3; blk++){
    int Tb = Told-2;
    long TN = (long)Tb*Nx;
    long totd = (long)Bx*Cx*TN;
    k_xmean<<<(int)divup(Bx*Cx*Nx,256),256>>>(Xcur, Told);
    k_escore<<<(int)divup(Bx*Ex,128),128>>>(idx, vsf+blk*Cx, vdf+blk*Cx, vsb+blk*Cx, vdb+blk*Cx);
    k_edge1<<<(int)divup(Bx*EHx,128),128>>>(G0);
    k_edge2<<<(int)divup(Bx*Ex,128),128>>>(G1, wef, web);
    k_dconv<<<(int)divup(totd,256),256>>>(Xcur, Told, fw+blk*Cx*Cx*2, fb+blk*Cx,
                                          gw+blk*Cx*Cx*2, gb+blk*Cx, Tb);
    k_shop<<<(int)divup(totd,256),256>>>(Tb, 0,   40, 1);
    k_shop<<<(int)divup(totd,256),256>>>(Tb, 40,  80, 1);
    k_shop<<<(int)divup(totd,256),256>>>(Tb, 0,  120, 0);
    k_shop<<<(int)divup(totd,256),256>>>(Tb, 120,160, 0);
    {
      dim3 gr((unsigned)divup(Nx,64),(unsigned)divup(Cx*Tb,64),Bx);
      k_gemm<<<gr,256>>>(H,          ADP, H+200*TN, Cx*Tb, Nx, Nx, 7*Cx*TN, 0, 7*Cx*TN, 0,0,0,0,0,0);
      k_gemm<<<gr,256>>>(H+200*TN,   ADP, H+240*TN, Cx*Tb, Nx, Nx, 7*Cx*TN, 0, 7*Cx*TN, 0,0,0,0,0,0);
    }
    {
      dim3 gr((unsigned)divup(TN,64),1,Bx);
      k_gemm<<<gr,256>>>(WT+blk*Cx*7*Cx, H, G, Cx, (int)TN, 7*Cx, 0, 7*Cx*TN, Cx*TN,
                         gcb+blk*Cx, 0,0,0,0,0);
    }
    k_bnstats<<<Cx,256>>>(G, Tb);
    k_bnapply1<<<(int)divup(totd,256),256>>>(G, Xcur, Told, Xnext, Tb, bgg+blk*Cx, bgb+blk*Cx);
    k_bnstats<<<Cx,256>>>(Xnext, Tb);
    k_bnapply2<<<(int)divup(totd,256),256>>>(Xnext, Tb, bng+blk*Cx, bnb+blk*Cx);
    {
      dim3 gr((unsigned)divup(TN,64),(unsigned)divup(320,64),Bx);
      if (blk==0)
        k_gemm<<<gr,256>>>(skw, Xnext, Scur, 320, (int)TN, Cx, 0, Cx*TN, 320*TN,
                           skb, 0,0,0,0,0);
      else
        k_gemm<<<gr,256>>>(skw+blk*320*Cx, Xnext, Scur, 320, (int)TN, Cx, 0, Cx*TN, 320*TN,
                           skb+blk*320, Sprev, 320L*Tprev*Nx, Tprev*Nx, 2*Nx, 0);
    }
    float* tmp = Xcur; Xcur = Xnext; Xnext = tmp;
    Sprev = Scur; Scur = (Scur==S1)? S2 : S1;
    Tprev = Tb; Told = Tb;
  }
  long TNf = 7L*Nx;
  long stot = (long)Bx*320*TNf;
  k_leaky<<<(int)divup(stot,256),256>>>(Sprev, stot);
  {
    dim3 gr((unsigned)divup(TNf,64),(unsigned)divup(640,64),Bx);
    k_gemm<<<gr,256>>>(e1w, Sprev, E1, 640, (int)TNf, 320, 0, 320*TNf, 640*TNf,
                       e1b, 0,0,0,0, 1);
  }
  k_end2<<<(int)divup((long)Bx*12*TNf,128),128>>>(e2w, e2b, out);
}